// round 1
// baseline (speedup 1.0000x reference)
#include <cuda_runtime.h>

// Shapes fixed by the problem
#define B_DIM 512
#define T_DIM 400
#define V_DIM 32000
#define ENC_DIM 1024
#define HID_DIM 1024
#define EMB_DIM 512

#define NTHREADS 512

__global__ __launch_bounds__(NTHREADS)
void pointer_generator_kernel(
    const float* __restrict__ vocab_dist,   // [B, V]
    const float* __restrict__ attn_dist,    // [B, T]
    const float* __restrict__ context,      // [B, ENC]
    const float* __restrict__ state,        // [B, HID]
    const float* __restrict__ emb,          // [B, EMB]
    const int*   __restrict__ src_ids,      // [B, T]
    const int*   __restrict__ vocab_size_p, // scalar
    const float* __restrict__ w_c,          // [ENC]
    const float* __restrict__ w_s,          // [HID]
    const float* __restrict__ w_y,          // [EMB]
    const float* __restrict__ b_p,          // [1]
    float*       __restrict__ out)          // [B, V]
{
    const int row = blockIdx.x;
    const int tid = threadIdx.x;

    // ---------------- Phase 1: p_gen reduction ----------------
    float acc = 0.0f;

    {
        const float4* c4 = reinterpret_cast<const float4*>(context + (size_t)row * ENC_DIM);
        const float4* w4 = reinterpret_cast<const float4*>(w_c);
        #pragma unroll 2
        for (int i = tid; i < ENC_DIM / 4; i += NTHREADS) {
            float4 a = c4[i], w = w4[i];
            acc += a.x * w.x + a.y * w.y + a.z * w.z + a.w * w.w;
        }
    }
    {
        const float4* s4 = reinterpret_cast<const float4*>(state + (size_t)row * HID_DIM);
        const float4* w4 = reinterpret_cast<const float4*>(w_s);
        #pragma unroll 2
        for (int i = tid; i < HID_DIM / 4; i += NTHREADS) {
            float4 a = s4[i], w = w4[i];
            acc += a.x * w.x + a.y * w.y + a.z * w.z + a.w * w.w;
        }
    }
    {
        const float4* e4 = reinterpret_cast<const float4*>(emb + (size_t)row * EMB_DIM);
        const float4* w4 = reinterpret_cast<const float4*>(w_y);
        #pragma unroll 2
        for (int i = tid; i < EMB_DIM / 4; i += NTHREADS) {
            float4 a = e4[i], w = w4[i];
            acc += a.x * w.x + a.y * w.y + a.z * w.z + a.w * w.w;
        }
    }

    // warp reduce
    #pragma unroll
    for (int off = 16; off > 0; off >>= 1)
        acc += __shfl_down_sync(0xffffffffu, acc, off);

    __shared__ float s_partial[NTHREADS / 32];
    __shared__ float s_pgen;
    const int lane = tid & 31;
    const int wid  = tid >> 5;
    if (lane == 0) s_partial[wid] = acc;
    __syncthreads();
    if (tid == 0) {
        float total = 0.0f;
        #pragma unroll
        for (int i = 0; i < NTHREADS / 32; i++) total += s_partial[i];
        total += b_p[0];
        // sigmoid
        s_pgen = 1.0f / (1.0f + __expf(-total));
    }
    __syncthreads();

    const float p_gen  = s_pgen;
    const float p_copy = 1.0f - p_gen;

    // ---------------- Phase 2: scale vocab_dist ----------------
    {
        const float4* v4 = reinterpret_cast<const float4*>(vocab_dist + (size_t)row * V_DIM);
        float4*       o4 = reinterpret_cast<float4*>(out + (size_t)row * V_DIM);
        #pragma unroll 4
        for (int i = tid; i < V_DIM / 4; i += NTHREADS) {
            float4 x = v4[i];
            x.x *= p_gen; x.y *= p_gen; x.z *= p_gen; x.w *= p_gen;
            o4[i] = x;
        }
    }

    // Block-scope ordering: all of this row's scaled writes are visible to the
    // block's atomics after the barrier. Scatter targets only this row, so no
    // cross-CTA hazard exists.
    __syncthreads();

    // ---------------- Phase 3: masked scatter-add ----------------
    const int vsz = *vocab_size_p;
    if (tid < T_DIM) {
        // T=400 < 512 threads: single pass
        const int   id = src_ids[(size_t)row * T_DIM + tid];
        if (id < vsz) {
            const float a = attn_dist[(size_t)row * T_DIM + tid];
            atomicAdd(out + (size_t)row * V_DIM + id, p_copy * a);
        }
    }
}

extern "C" void kernel_launch(void* const* d_in, const int* in_sizes, int n_in,
                              void* d_out, int out_size) {
    const float* vocab_dist = (const float*)d_in[0];
    const float* attn_dist  = (const float*)d_in[1];
    const float* context    = (const float*)d_in[2];
    const float* state      = (const float*)d_in[3];
    const float* emb        = (const float*)d_in[4];
    const int*   src_ids    = (const int*)d_in[5];
    const int*   vocab_size = (const int*)d_in[6];
    const float* w_c        = (const float*)d_in[7];
    const float* w_s        = (const float*)d_in[8];
    const float* w_y        = (const float*)d_in[9];
    const float* b          = (const float*)d_in[10];
    float*       out        = (float*)d_out;

    pointer_generator_kernel<<<B_DIM, NTHREADS>>>(
        vocab_dist, attn_dist, context, state, emb, src_ids, vocab_size,
        w_c, w_s, w_y, b, out);
}